// round 1
// baseline (speedup 1.0000x reference)
#include <cuda_runtime.h>
#include <math.h>
#include <stdint.h>

// ---------------- problem constants ----------------
#define NNODES_MAX 50000
#define EEDGES_MAX 500000
#define ETOT_MAX   (EEDGES_MAX + NNODES_MAX)
#define FIN    128
#define HID    384
#define NH     8
#define CH     48
#define NEG_SLOPE 0.2f

// ---------------- scratch (device globals; no allocation) ----------------
__device__ float d_xl[(size_t)NNODES_MAX * HID];
__device__ float d_xr[(size_t)NNODES_MAX * HID];
__device__ float d_h1[(size_t)NNODES_MAX * HID];
__device__ float d_h2[(size_t)NNODES_MAX * HID];
__device__ float d_sc[(size_t)ETOT_MAX * NH];     // edge scores -> exp values (in place)
__device__ float d_mx[(size_t)NNODES_MAX * NH];   // segment max
__device__ float d_dn[(size_t)NNODES_MAX * NH];   // segment denom

// ---------------- helpers ----------------
__device__ __forceinline__ void atomicMaxFloat(float* addr, float v) {
    // valid for non-NaN values; init must be -inf (0xFF800000)
    if (v >= 0.0f) atomicMax((int*)addr, __float_as_int(v));
    else           atomicMin((unsigned int*)addr, __float_as_uint(v));
}

__device__ __forceinline__ void edge_sd(const int* __restrict__ ei, int e, int E,
                                        int& s, int& d) {
    if (e < E) { s = ei[e]; d = ei[E + e]; }
    else       { s = e - E; d = s; }        // self loops appended
}

__global__ void fill_kernel(float* __restrict__ p, float v, int n) {
    int i = blockIdx.x * blockDim.x + threadIdx.x;
    if (i < n) p[i] = v;
}

// ---------------- GEMM: C[n,m] = A[n,k] @ W[k,m] + bias[m] ----------------
// BM=128, BN=64, BK=16, 256 threads, thread tile 8x4
#define BM 128
#define BN 64
#define BK 16

__global__ __launch_bounds__(256)
void gemm_bias(const float* __restrict__ A, const float* __restrict__ W,
               const float* __restrict__ bias, float* __restrict__ C,
               int Nrows, int K, int M) {
    __shared__ float As[BK][BM + 4];
    __shared__ float Bs[BK][BN];

    const int block_row = blockIdx.x * BM;
    const int block_col = blockIdx.y * BN;
    const int tid = threadIdx.x;
    const int ty = tid >> 4;      // 0..15 -> row group of 8
    const int tx = tid & 15;      // 0..15 -> col group of 4

    float acc[8][4];
#pragma unroll
    for (int i = 0; i < 8; i++)
#pragma unroll
        for (int j = 0; j < 4; j++) acc[i][j] = 0.0f;

    const int ktiles = K / BK;
    for (int t = 0; t < ktiles; t++) {
        const int k0 = t * BK;
        // load A tile: 128x16 = 2048 elems, 8 per thread
#pragma unroll
        for (int l = 0; l < 8; l++) {
            int elem = tid + l * 256;
            int arow = elem >> 4;
            int acol = elem & 15;
            int grow = block_row + arow;
            float v = 0.0f;
            if (grow < Nrows) v = A[(size_t)grow * K + k0 + acol];
            As[acol][arow] = v;
        }
        // load B tile: 16x64 = 1024 elems, 4 per thread
#pragma unroll
        for (int l = 0; l < 4; l++) {
            int elem = tid + l * 256;
            int brow = elem >> 6;
            int bcol = elem & 63;
            Bs[brow][bcol] = W[(size_t)(k0 + brow) * M + block_col + bcol];
        }
        __syncthreads();

#pragma unroll
        for (int kk = 0; kk < BK; kk++) {
            float4 a0 = *(const float4*)&As[kk][ty * 8];
            float4 a1 = *(const float4*)&As[kk][ty * 8 + 4];
            float4 b  = *(const float4*)&Bs[kk][tx * 4];
            float ra[8] = {a0.x, a0.y, a0.z, a0.w, a1.x, a1.y, a1.z, a1.w};
            float rb[4] = {b.x, b.y, b.z, b.w};
#pragma unroll
            for (int i = 0; i < 8; i++)
#pragma unroll
                for (int j = 0; j < 4; j++) acc[i][j] += ra[i] * rb[j];
        }
        __syncthreads();
    }

    // write out
#pragma unroll
    for (int i = 0; i < 8; i++) {
        int r = block_row + ty * 8 + i;
        if (r < Nrows) {
#pragma unroll
            for (int j = 0; j < 4; j++) {
                int c = block_col + tx * 4 + j;
                C[(size_t)r * M + c] = acc[i][j] + bias[c];
            }
        }
    }
}

// ---------------- edge score + segment max (layers 1,2) ----------------
// one warp per edge; lane owns 12 contiguous channels (exactly 1/4 of a head)
__global__ void score_kernel(const float* __restrict__ xl, const float* __restrict__ xr,
                             const int* __restrict__ ei, const float* __restrict__ att,
                             float* __restrict__ score, float* __restrict__ smax,
                             int E, int Etot) {
    int e = (blockIdx.x * blockDim.x + threadIdx.x) >> 5;
    if (e >= Etot) return;
    int lane = threadIdx.x & 31;
    int s, d;
    edge_sd(ei, e, E, s, d);
    const float4* pl = (const float4*)(xl + (size_t)s * HID) + lane * 3;
    const float4* pr = (const float4*)(xr + (size_t)d * HID) + lane * 3;
    const float4* pa = (const float4*)att + lane * 3;
    float partial = 0.0f;
#pragma unroll
    for (int i = 0; i < 3; i++) {
        float4 a = pl[i], b = pr[i], w = pa[i];
        float m;
        m = a.x + b.x; partial += (m > 0.f ? m : NEG_SLOPE * m) * w.x;
        m = a.y + b.y; partial += (m > 0.f ? m : NEG_SLOPE * m) * w.y;
        m = a.z + b.z; partial += (m > 0.f ? m : NEG_SLOPE * m) * w.z;
        m = a.w + b.w; partial += (m > 0.f ? m : NEG_SLOPE * m) * w.w;
    }
    partial += __shfl_xor_sync(0xffffffffu, partial, 1);
    partial += __shfl_xor_sync(0xffffffffu, partial, 2);
    if ((lane & 3) == 0) {
        int h = lane >> 2;
        score[(size_t)e * NH + h] = partial;
        atomicMaxFloat(&smax[(size_t)d * NH + h], partial);
    }
}

// ---------------- exp + segment denom (layers 1,2) ----------------
__global__ void softmax_e_kernel(float* __restrict__ score, const float* __restrict__ smax,
                                 float* __restrict__ denom, const int* __restrict__ ei,
                                 int E, int Etot) {
    int idx = blockIdx.x * blockDim.x + threadIdx.x;
    if (idx >= Etot * NH) return;
    int e = idx >> 3;
    int h = idx & 7;
    int s, d;
    edge_sd(ei, e, E, s, d);
    float ex = expf(score[idx] - smax[(size_t)d * NH + h]);
    score[idx] = ex;
    atomicAdd(&denom[(size_t)d * NH + h], ex);
}

// ---------------- aggregation: out[d] += xl[s] * alpha (layers 1,2) ----------------
__global__ void agg_kernel(const float* __restrict__ xl, const int* __restrict__ ei,
                           const float* __restrict__ ex, const float* __restrict__ denom,
                           float* __restrict__ out, int E, int Etot) {
    int e = (blockIdx.x * blockDim.x + threadIdx.x) >> 5;
    if (e >= Etot) return;
    int lane = threadIdx.x & 31;
    int s, d;
    edge_sd(ei, e, E, s, d);
    int h = lane >> 2;
    float alpha = ex[(size_t)e * NH + h] / (denom[(size_t)d * NH + h] + 1e-16f);
    const float4* pl = (const float4*)(xl + (size_t)s * HID) + lane * 3;
    float* po = out + (size_t)d * HID + lane * 12;
#pragma unroll
    for (int i = 0; i < 3; i++) {
        float4 a = pl[i];
        atomicAdd(po + i * 4 + 0, a.x * alpha);
        atomicAdd(po + i * 4 + 1, a.y * alpha);
        atomicAdd(po + i * 4 + 2, a.z * alpha);
        atomicAdd(po + i * 4 + 3, a.w * alpha);
    }
}

// ---------------- bias + ELU (layers 1,2) ----------------
__global__ void bias_elu_kernel(float* __restrict__ h, const float* __restrict__ bias, int n) {
    int idx = blockIdx.x * blockDim.x + threadIdx.x;
    if (idx >= n) return;
    float v = h[idx] + bias[idx % HID];
    h[idx] = v > 0.0f ? v : expm1f(v);
}

// ---------------- layer 3: linear 384 -> 2 (both Wl and Wr fused) ----------------
__global__ void lin3_kernel(const float* __restrict__ h,
                            const float* __restrict__ Wl, const float* __restrict__ bl,
                            const float* __restrict__ Wr, const float* __restrict__ br,
                            float* __restrict__ xl3, float* __restrict__ xr3, int n) {
    int w = (blockIdx.x * blockDim.x + threadIdx.x) >> 5;
    if (w >= n) return;
    int lane = threadIdx.x & 31;
    const float* row = h + (size_t)w * HID;
    float l0 = 0.f, l1 = 0.f, r0 = 0.f, r1 = 0.f;
    for (int k = lane; k < HID; k += 32) {
        float a = row[k];
        l0 += a * Wl[2 * k];     l1 += a * Wl[2 * k + 1];
        r0 += a * Wr[2 * k];     r1 += a * Wr[2 * k + 1];
    }
#pragma unroll
    for (int o = 16; o > 0; o >>= 1) {
        l0 += __shfl_xor_sync(0xffffffffu, l0, o);
        l1 += __shfl_xor_sync(0xffffffffu, l1, o);
        r0 += __shfl_xor_sync(0xffffffffu, r0, o);
        r1 += __shfl_xor_sync(0xffffffffu, r1, o);
    }
    if (lane == 0) {
        xl3[2 * w]     = l0 + bl[0];
        xl3[2 * w + 1] = l1 + bl[1];
        xr3[2 * w]     = r0 + br[0];
        xr3[2 * w + 1] = r1 + br[1];
    }
}

// ---------------- layer 3 edge phases (1 head, 2 ch) ----------------
__global__ void score3_kernel(const float* __restrict__ xl3, const float* __restrict__ xr3,
                              const int* __restrict__ ei, const float* __restrict__ att,
                              float* __restrict__ score, float* __restrict__ smax,
                              int E, int Etot) {
    int e = blockIdx.x * blockDim.x + threadIdx.x;
    if (e >= Etot) return;
    int s, d;
    edge_sd(ei, e, E, s, d);
    float m0 = xl3[2 * s] + xr3[2 * d];
    float m1 = xl3[2 * s + 1] + xr3[2 * d + 1];
    float sc = (m0 > 0.f ? m0 : NEG_SLOPE * m0) * att[0]
             + (m1 > 0.f ? m1 : NEG_SLOPE * m1) * att[1];
    score[e] = sc;
    atomicMaxFloat(&smax[d], sc);
}

__global__ void softmax3_kernel(float* __restrict__ score, const float* __restrict__ smax,
                                float* __restrict__ denom, const int* __restrict__ ei,
                                int E, int Etot) {
    int e = blockIdx.x * blockDim.x + threadIdx.x;
    if (e >= Etot) return;
    int s, d;
    edge_sd(ei, e, E, s, d);
    float ex = expf(score[e] - smax[d]);
    score[e] = ex;
    atomicAdd(&denom[d], ex);
}

__global__ void agg3_kernel(const float* __restrict__ xl3, const int* __restrict__ ei,
                            const float* __restrict__ ex, const float* __restrict__ denom,
                            float* __restrict__ out, int E, int Etot) {
    int e = blockIdx.x * blockDim.x + threadIdx.x;
    if (e >= Etot) return;
    int s, d;
    edge_sd(ei, e, E, s, d);
    float alpha = ex[e] / (denom[d] + 1e-16f);
    atomicAdd(&out[2 * d],     xl3[2 * s]     * alpha);
    atomicAdd(&out[2 * d + 1], xl3[2 * s + 1] * alpha);
}

__global__ void logsoftmax_kernel(float* __restrict__ out, const float* __restrict__ bias, int n) {
    int i = blockIdx.x * blockDim.x + threadIdx.x;
    if (i >= n) return;
    float a = out[2 * i] + bias[0];
    float b = out[2 * i + 1] + bias[1];
    float m = fmaxf(a, b);
    float l = m + logf(expf(a - m) + expf(b - m));
    out[2 * i]     = a - l;
    out[2 * i + 1] = b - l;
}

// ---------------- host side ----------------
static inline int cdiv(int a, int b) { return (a + b - 1) / b; }

static void run_layer(const float* in, int K, const int* ei, int E, int Etot, int n,
                      const float* Wl, const float* bl, const float* Wr, const float* br,
                      const float* att, const float* bias,
                      float* xl, float* xr, float* score, float* smax, float* denom,
                      float* out) {
    dim3 gg(cdiv(n, BM), HID / BN);
    gemm_bias<<<gg, 256>>>(in, Wl, bl, xl, n, K, HID);
    gemm_bias<<<gg, 256>>>(in, Wr, br, xr, n, K, HID);
    fill_kernel<<<cdiv(n * NH, 256), 256>>>(smax, -INFINITY, n * NH);
    fill_kernel<<<cdiv(n * NH, 256), 256>>>(denom, 0.0f, n * NH);
    fill_kernel<<<cdiv(n * HID, 256), 256>>>(out, 0.0f, n * HID);
    score_kernel<<<cdiv(Etot * 32, 256), 256>>>(xl, xr, ei, att, score, smax, E, Etot);
    softmax_e_kernel<<<cdiv(Etot * NH, 256), 256>>>(score, smax, denom, ei, E, Etot);
    agg_kernel<<<cdiv(Etot * 32, 256), 256>>>(xl, ei, score, denom, out, E, Etot);
    bias_elu_kernel<<<cdiv(n * HID, 256), 256>>>(out, bias, n * HID);
}

extern "C" void kernel_launch(void* const* d_in, const int* in_sizes, int n_in,
                              void* d_out, int out_size) {
    const float* x   = (const float*)d_in[0];
    const int*   ei  = (const int*)d_in[1];
    const float* Wl1 = (const float*)d_in[2];
    const float* bl1 = (const float*)d_in[3];
    const float* Wr1 = (const float*)d_in[4];
    const float* br1 = (const float*)d_in[5];
    const float* att1  = (const float*)d_in[6];
    const float* bias1 = (const float*)d_in[7];
    const float* Wl2 = (const float*)d_in[8];
    const float* bl2 = (const float*)d_in[9];
    const float* Wr2 = (const float*)d_in[10];
    const float* br2 = (const float*)d_in[11];
    const float* att2  = (const float*)d_in[12];
    const float* bias2 = (const float*)d_in[13];
    const float* Wl3 = (const float*)d_in[14];
    const float* bl3 = (const float*)d_in[15];
    const float* Wr3 = (const float*)d_in[16];
    const float* br3 = (const float*)d_in[17];
    const float* att3  = (const float*)d_in[18];
    const float* bias3 = (const float*)d_in[19];

    const int n    = in_sizes[0] / FIN;       // 50000
    const int E    = in_sizes[1] / 2;         // 500000
    const int Etot = E + n;                   // 550000

    float *xl, *xr, *h1, *h2, *sc, *mx, *dn;
    cudaGetSymbolAddress((void**)&xl, d_xl);
    cudaGetSymbolAddress((void**)&xr, d_xr);
    cudaGetSymbolAddress((void**)&h1, d_h1);
    cudaGetSymbolAddress((void**)&h2, d_h2);
    cudaGetSymbolAddress((void**)&sc, d_sc);
    cudaGetSymbolAddress((void**)&mx, d_mx);
    cudaGetSymbolAddress((void**)&dn, d_dn);
    float* out = (float*)d_out;

    // ---- layer 1: x (128) -> h1 (384) ----
    run_layer(x, FIN, ei, E, Etot, n, Wl1, bl1, Wr1, br1, att1, bias1,
              xl, xr, sc, mx, dn, h1);
    // ---- layer 2: h1 (384) -> h2 (384) ----
    run_layer(h1, HID, ei, E, Etot, n, Wl2, bl2, Wr2, br2, att2, bias2,
              xl, xr, sc, mx, dn, h2);

    // ---- layer 3: h2 (384) -> 2, 1 head, concat=False ----
    // reuse xl/xr front as xl3/xr3, sc as score3, mx/dn front as smax3/denom3
    lin3_kernel<<<cdiv(n * 32, 256), 256>>>(h2, Wl3, bl3, Wr3, br3, xl, xr, n);
    fill_kernel<<<cdiv(n, 256), 256>>>(mx, -INFINITY, n);
    fill_kernel<<<cdiv(n, 256), 256>>>(dn, 0.0f, n);
    fill_kernel<<<cdiv(2 * n, 256), 256>>>(out, 0.0f, 2 * n);
    score3_kernel<<<cdiv(Etot, 256), 256>>>(xl, xr, ei, att3, sc, mx, E, Etot);
    softmax3_kernel<<<cdiv(Etot, 256), 256>>>(sc, mx, dn, ei, E, Etot);
    agg3_kernel<<<cdiv(Etot, 256), 256>>>(xl, ei, sc, dn, out, E, Etot);
    logsoftmax_kernel<<<cdiv(n, 256), 256>>>(out, bias3, n);
}

// round 3
// speedup vs baseline: 2.6503x; 2.6503x over previous
#include <cuda_runtime.h>
#include <math.h>
#include <stdint.h>

// ---------------- problem constants ----------------
#define NNODES_MAX 50000
#define EEDGES_MAX 500000
#define ETOT_MAX   (EEDGES_MAX + NNODES_MAX)
#define FIN    128
#define HID    384
#define NH     8
#define CH     48
#define NEG_SLOPE 0.2f

// ---------------- scratch (device globals; no allocation) ----------------
__device__ float d_xl[(size_t)NNODES_MAX * HID];
__device__ float d_xr[(size_t)NNODES_MAX * HID];
__device__ float d_h1[(size_t)NNODES_MAX * HID];
__device__ float d_h2[(size_t)NNODES_MAX * HID];
__device__ int   d_cnt[NNODES_MAX];
__device__ int   d_rowptr[NNODES_MAX + 1];
__device__ int   d_cur[NNODES_MAX];
__device__ int   d_csr[ETOT_MAX];

// ---------------- helpers ----------------
__device__ __forceinline__ void edge_sd(const int* __restrict__ ei, int e, int E,
                                        int& s, int& d) {
    if (e < E) { s = ei[e]; d = ei[E + e]; }
    else       { s = e - E; d = s; }        // self loops appended
}

__global__ void zero_int_kernel(int* __restrict__ p, int n) {
    int i = blockIdx.x * blockDim.x + threadIdx.x;
    if (i < n) p[i] = 0;
}

// ---------------- CSR build ----------------
__global__ void hist_kernel(const int* __restrict__ ei, int* __restrict__ cnt,
                            int E, int Etot) {
    int e = blockIdx.x * blockDim.x + threadIdx.x;
    if (e >= Etot) return;
    int s, d;
    edge_sd(ei, e, E, s, d);
    atomicAdd(&cnt[d], 1);
}

// single-block exclusive scan over n elements
__global__ void scan_kernel(const int* __restrict__ cnt, int* __restrict__ rowptr,
                            int* __restrict__ cursor, int n) {
    __shared__ int sdata[1024];
    __shared__ int carry;
    int tid = threadIdx.x;
    if (tid == 0) { carry = 0; rowptr[0] = 0; }
    __syncthreads();
    for (int base = 0; base < n; base += 1024) {
        int i = base + tid;
        int v = (i < n) ? cnt[i] : 0;
        sdata[tid] = v;
        __syncthreads();
#pragma unroll
        for (int off = 1; off < 1024; off <<= 1) {
            int t = (tid >= off) ? sdata[tid - off] : 0;
            __syncthreads();
            sdata[tid] += t;
            __syncthreads();
        }
        if (i < n) {
            int incl = carry + sdata[tid];
            rowptr[i + 1] = incl;
            cursor[i] = incl - v;   // exclusive prefix = row start
        }
        __syncthreads();
        if (tid == 0) carry += sdata[1023];
        __syncthreads();
    }
}

__global__ void scatter_kernel(const int* __restrict__ ei, int* __restrict__ cursor,
                               int* __restrict__ csr, int E, int Etot) {
    int e = blockIdx.x * blockDim.x + threadIdx.x;
    if (e >= Etot) return;
    int s, d;
    edge_sd(ei, e, E, s, d);
    int pos = atomicAdd(&cursor[d], 1);
    csr[pos] = s;
}

// ---------------- GEMM: C[n,m] = A[n,k] @ W[k,m] + bias[m] ----------------
// 128x128 block tile, BK=8, 256 threads, 8x8 per-thread tile,
// double-buffered smem (one __syncthreads per k-tile).
#define GBM 128
#define GBN 128
#define GBK 8

__global__ __launch_bounds__(256)
void gemm_bias2(const float* __restrict__ A, const float* __restrict__ W,
                const float* __restrict__ bias, float* __restrict__ C,
                int Nrows, int K, int M) {
    __shared__ float As[2][GBK][GBM + 4];
    __shared__ float Bs[2][GBK][GBN];

    const int block_row = blockIdx.x * GBM;
    const int block_col = blockIdx.y * GBN;
    const int tid = threadIdx.x;
    const int ty = tid >> 4;      // 0..15
    const int tx = tid & 15;      // 0..15

    float acc[8][8];
#pragma unroll
    for (int i = 0; i < 8; i++)
#pragma unroll
        for (int j = 0; j < 8; j++) acc[i][j] = 0.0f;

    // A tile load mapping: one float4 per thread. 128 rows x 8 cols.
    const int arow = tid >> 1;
    const int acol = (tid & 1) * 4;
    const int grow = block_row + arow;
    // B tile load mapping: one float4 per thread. 8 rows x 128 cols.
    const int brl = tid >> 5;
    const int bcl = (tid & 31) * 4;

    const int ktiles = K / GBK;

    // preload tile 0
    {
        float4 av = make_float4(0.f, 0.f, 0.f, 0.f);
        if (grow < Nrows) av = *(const float4*)&A[(size_t)grow * K + acol];
        As[0][acol + 0][arow] = av.x;
        As[0][acol + 1][arow] = av.y;
        As[0][acol + 2][arow] = av.z;
        As[0][acol + 3][arow] = av.w;
        *(float4*)&Bs[0][brl][bcl] = *(const float4*)&W[(size_t)brl * M + block_col + bcl];
    }
    __syncthreads();

    int buf = 0;
    for (int t = 0; t < ktiles; t++) {
        const bool has_next = (t + 1 < ktiles);
        float4 avn = make_float4(0.f, 0.f, 0.f, 0.f);
        float4 bvn = make_float4(0.f, 0.f, 0.f, 0.f);
        if (has_next) {
            const int k0n = (t + 1) * GBK;
            if (grow < Nrows) avn = *(const float4*)&A[(size_t)grow * K + k0n + acol];
            bvn = *(const float4*)&W[(size_t)(k0n + brl) * M + block_col + bcl];
        }

#pragma unroll
        for (int kk = 0; kk < GBK; kk++) {
            float4 a0 = *(const float4*)&As[buf][kk][ty * 8];
            float4 a1 = *(const float4*)&As[buf][kk][ty * 8 + 4];
            float4 b0 = *(const float4*)&Bs[buf][kk][tx * 8];
            float4 b1 = *(const float4*)&Bs[buf][kk][tx * 8 + 4];
            float ra[8] = {a0.x, a0.y, a0.z, a0.w, a1.x, a1.y, a1.z, a1.w};
            float rb[8] = {b0.x, b0.y, b0.z, b0.w, b1.x, b1.y, b1.z, b1.w};
#pragma unroll
            for (int i = 0; i < 8; i++)
#pragma unroll
                for (int j = 0; j < 8; j++) acc[i][j] += ra[i] * rb[j];
        }

        if (has_next) {
            const int nb = buf ^ 1;
            As[nb][acol + 0][arow] = avn.x;
            As[nb][acol + 1][arow] = avn.y;
            As[nb][acol + 2][arow] = avn.z;
            As[nb][acol + 3][arow] = avn.w;
            *(float4*)&Bs[nb][brl][bcl] = bvn;
        }
        __syncthreads();
        buf ^= 1;
    }

#pragma unroll
    for (int i = 0; i < 8; i++) {
        int r = block_row + ty * 8 + i;
        if (r < Nrows) {
            int c0 = block_col + tx * 8;
            float4 o0, o1;
            o0.x = acc[i][0] + bias[c0 + 0];
            o0.y = acc[i][1] + bias[c0 + 1];
            o0.z = acc[i][2] + bias[c0 + 2];
            o0.w = acc[i][3] + bias[c0 + 3];
            o1.x = acc[i][4] + bias[c0 + 4];
            o1.y = acc[i][5] + bias[c0 + 5];
            o1.z = acc[i][6] + bias[c0 + 6];
            o1.w = acc[i][7] + bias[c0 + 7];
            *(float4*)&C[(size_t)r * M + c0]     = o0;
            *(float4*)&C[(size_t)r * M + c0 + 4] = o1;
        }
    }
}

// ---------------- fused per-node GATv2 edge phase (layers 1,2) ----------------
// one warp per node; lane owns 12 contiguous channels (1/4 of one head).
// Online softmax over incoming edges; prefetch next edge's source row.
__global__ __launch_bounds__(256)
void gat_node_kernel(const float* __restrict__ xl, const float* __restrict__ xr,
                     const float* __restrict__ att, const float* __restrict__ bias,
                     const int* __restrict__ rowptr, const int* __restrict__ csr,
                     float* __restrict__ out, int n) {
    int node = (blockIdx.x * blockDim.x + threadIdx.x) >> 5;
    if (node >= n) return;
    int lane = threadIdx.x & 31;

    const float4* pr = (const float4*)(xr + (size_t)node * HID) + lane * 3;
    float4 r0 = pr[0], r1 = pr[1], r2 = pr[2];
    const float4* pa = (const float4*)att + lane * 3;
    float4 a0 = pa[0], a1 = pa[1], a2 = pa[2];

    float ra[12] = {r0.x, r0.y, r0.z, r0.w, r1.x, r1.y, r1.z, r1.w, r2.x, r2.y, r2.z, r2.w};
    float wa[12] = {a0.x, a0.y, a0.z, a0.w, a1.x, a1.y, a1.z, a1.w, a2.x, a2.y, a2.z, a2.w};

    float m = -INFINITY, ssum = 0.0f;
    float acc[12];
#pragma unroll
    for (int k = 0; k < 12; k++) acc[k] = 0.0f;

    const int jbeg = rowptr[node], jend = rowptr[node + 1];

    // prefetch first edge
    float4 n0, n1, n2;
    if (jbeg < jend) {
        int s0 = csr[jbeg];
        const float4* pl = (const float4*)(xl + (size_t)s0 * HID) + lane * 3;
        n0 = pl[0]; n1 = pl[1]; n2 = pl[2];
    }

    for (int j = jbeg; j < jend; j++) {
        float4 l0 = n0, l1 = n1, l2 = n2;
        if (j + 1 < jend) {
            int s2 = csr[j + 1];
            const float4* pl = (const float4*)(xl + (size_t)s2 * HID) + lane * 3;
            n0 = pl[0]; n1 = pl[1]; n2 = pl[2];
        }
        float la[12] = {l0.x, l0.y, l0.z, l0.w, l1.x, l1.y, l1.z, l1.w, l2.x, l2.y, l2.z, l2.w};

        float partial = 0.0f;
#pragma unroll
        for (int k = 0; k < 12; k++) {
            float mv = la[k] + ra[k];
            partial += (mv > 0.f ? mv : NEG_SLOPE * mv) * wa[k];
        }
        // reduce over the 4 lanes of this head (lane groups aligned mod 4)
        partial += __shfl_xor_sync(0xffffffffu, partial, 1);
        partial += __shfl_xor_sync(0xffffffffu, partial, 2);

        float newm = fmaxf(m, partial);
        float scale = __expf(m - newm);        // 0 on first edge (m=-inf)
        float p = __expf(partial - newm);
        ssum = ssum * scale + p;
#pragma unroll
        for (int k = 0; k < 12; k++) acc[k] = acc[k] * scale + p * la[k];
        m = newm;
    }

    float inv = 1.0f / (ssum + 1e-16f);
    const float4* pb = (const float4*)bias + lane * 3;
    float4 b0 = pb[0], b1 = pb[1], b2 = pb[2];
    float ba[12] = {b0.x, b0.y, b0.z, b0.w, b1.x, b1.y, b1.z, b1.w, b2.x, b2.y, b2.z, b2.w};

    float o[12];
#pragma unroll
    for (int k = 0; k < 12; k++) {
        float v = acc[k] * inv + ba[k];
        o[k] = v > 0.0f ? v : expm1f(v);   // ELU
    }
    float4* po = (float4*)(out + (size_t)node * HID) + lane * 3;
    po[0] = make_float4(o[0], o[1], o[2], o[3]);
    po[1] = make_float4(o[4], o[5], o[6], o[7]);
    po[2] = make_float4(o[8], o[9], o[10], o[11]);
}

// ---------------- layer 3: linear 384 -> 2 (Wl and Wr fused) ----------------
__global__ void lin3_kernel(const float* __restrict__ h,
                            const float* __restrict__ Wl, const float* __restrict__ bl,
                            const float* __restrict__ Wr, const float* __restrict__ br,
                            float* __restrict__ xl3, float* __restrict__ xr3, int n) {
    int w = (blockIdx.x * blockDim.x + threadIdx.x) >> 5;
    if (w >= n) return;
    int lane = threadIdx.x & 31;
    const float* row = h + (size_t)w * HID;
    float l0 = 0.f, l1 = 0.f, r0 = 0.f, r1 = 0.f;
    for (int k = lane; k < HID; k += 32) {
        float a = row[k];
        l0 += a * Wl[2 * k];     l1 += a * Wl[2 * k + 1];
        r0 += a * Wr[2 * k];     r1 += a * Wr[2 * k + 1];
    }
#pragma unroll
    for (int o = 16; o > 0; o >>= 1) {
        l0 += __shfl_xor_sync(0xffffffffu, l0, o);
        l1 += __shfl_xor_sync(0xffffffffu, l1, o);
        r0 += __shfl_xor_sync(0xffffffffu, r0, o);
        r1 += __shfl_xor_sync(0xffffffffu, r1, o);
    }
    if (lane == 0) {
        xl3[2 * w]     = l0 + bl[0];
        xl3[2 * w + 1] = l1 + bl[1];
        xr3[2 * w]     = r0 + br[0];
        xr3[2 * w + 1] = r1 + br[1];
    }
}

// ---------------- layer 3 fused node kernel (1 head, 2 ch) + log_softmax ----------------
__global__ void gat3_node_kernel(const float* __restrict__ xl3, const float* __restrict__ xr3,
                                 const float* __restrict__ att3, const float* __restrict__ bias3,
                                 const int* __restrict__ rowptr, const int* __restrict__ csr,
                                 float* __restrict__ out, int n) {
    int node = blockIdx.x * blockDim.x + threadIdx.x;
    if (node >= n) return;
    float rx0 = xr3[2 * node], rx1 = xr3[2 * node + 1];
    float w0 = att3[0], w1 = att3[1];
    float m = -INFINITY, ssum = 0.f, acc0 = 0.f, acc1 = 0.f;
    int jbeg = rowptr[node], jend = rowptr[node + 1];
    for (int j = jbeg; j < jend; j++) {
        int s = csr[j];
        float l0 = xl3[2 * s], l1 = xl3[2 * s + 1];
        float m0 = l0 + rx0, m1 = l1 + rx1;
        float sc = (m0 > 0.f ? m0 : NEG_SLOPE * m0) * w0
                 + (m1 > 0.f ? m1 : NEG_SLOPE * m1) * w1;
        float newm = fmaxf(m, sc);
        float scale = __expf(m - newm);
        float p = __expf(sc - newm);
        ssum = ssum * scale + p;
        acc0 = acc0 * scale + p * l0;
        acc1 = acc1 * scale + p * l1;
        m = newm;
    }
    float inv = 1.0f / (ssum + 1e-16f);
    float a = acc0 * inv + bias3[0];
    float b = acc1 * inv + bias3[1];
    float mm = fmaxf(a, b);
    float l = mm + logf(expf(a - mm) + expf(b - mm));
    out[2 * node]     = a - l;
    out[2 * node + 1] = b - l;
}

// ---------------- host side ----------------
static inline int cdiv(int a, int b) { return (a + b - 1) / b; }

extern "C" void kernel_launch(void* const* d_in, const int* in_sizes, int n_in,
                              void* d_out, int out_size) {
    const float* x   = (const float*)d_in[0];
    const int*   ei  = (const int*)d_in[1];
    const float* Wl1 = (const float*)d_in[2];
    const float* bl1 = (const float*)d_in[3];
    const float* Wr1 = (const float*)d_in[4];
    const float* br1 = (const float*)d_in[5];
    const float* att1  = (const float*)d_in[6];
    const float* bias1 = (const float*)d_in[7];
    const float* Wl2 = (const float*)d_in[8];
    const float* bl2 = (const float*)d_in[9];
    const float* Wr2 = (const float*)d_in[10];
    const float* br2 = (const float*)d_in[11];
    const float* att2  = (const float*)d_in[12];
    const float* bias2 = (const float*)d_in[13];
    const float* Wl3 = (const float*)d_in[14];
    const float* bl3 = (const float*)d_in[15];
    const float* Wr3 = (const float*)d_in[16];
    const float* br3 = (const float*)d_in[17];
    const float* att3  = (const float*)d_in[18];
    const float* bias3 = (const float*)d_in[19];

    const int n    = in_sizes[0] / FIN;       // 50000
    const int E    = in_sizes[1] / 2;         // 500000
    const int Etot = E + n;                   // 550000

    float *xl, *xr, *h1, *h2;
    int *cnt, *rowptr, *cur, *csr;
    cudaGetSymbolAddress((void**)&xl, d_xl);
    cudaGetSymbolAddress((void**)&xr, d_xr);
    cudaGetSymbolAddress((void**)&h1, d_h1);
    cudaGetSymbolAddress((void**)&h2, d_h2);
    cudaGetSymbolAddress((void**)&cnt, d_cnt);
    cudaGetSymbolAddress((void**)&rowptr, d_rowptr);
    cudaGetSymbolAddress((void**)&cur, d_cur);
    cudaGetSymbolAddress((void**)&csr, d_csr);
    float* out = (float*)d_out;

    // ---- CSR build (shared by all 3 layers) ----
    zero_int_kernel<<<cdiv(n, 256), 256>>>(cnt, n);
    hist_kernel<<<cdiv(Etot, 256), 256>>>(ei, cnt, E, Etot);
    scan_kernel<<<1, 1024>>>(cnt, rowptr, cur, n);
    scatter_kernel<<<cdiv(Etot, 256), 256>>>(ei, cur, csr, E, Etot);

    // ---- layer 1: x (128) -> h1 (384) ----
    {
        dim3 gg(cdiv(n, GBM), HID / GBN);
        gemm_bias2<<<gg, 256>>>(x, Wl1, bl1, xl, n, FIN, HID);
        gemm_bias2<<<gg, 256>>>(x, Wr1, br1, xr, n, FIN, HID);
        gat_node_kernel<<<cdiv(n * 32, 256), 256>>>(xl, xr, att1, bias1, rowptr, csr, h1, n);
    }
    // ---- layer 2: h1 (384) -> h2 (384) ----
    {
        dim3 gg(cdiv(n, GBM), HID / GBN);
        gemm_bias2<<<gg, 256>>>(h1, Wl2, bl2, xl, n, HID, HID);
        gemm_bias2<<<gg, 256>>>(h1, Wr2, br2, xr, n, HID, HID);
        gat_node_kernel<<<cdiv(n * 32, 256), 256>>>(xl, xr, att2, bias2, rowptr, csr, h2, n);
    }
    // ---- layer 3: h2 (384) -> 2, 1 head, concat=False, + log_softmax ----
    lin3_kernel<<<cdiv(n * 32, 256), 256>>>(h2, Wl3, bl3, Wr3, br3, xl, xr, n);
    gat3_node_kernel<<<cdiv(n, 256), 256>>>(xl, xr, att3, bias3, rowptr, csr, out, n);
}

// round 5
// speedup vs baseline: 2.6778x; 1.0103x over previous
#include <cuda_runtime.h>
#include <math.h>
#include <stdint.h>

// ---------------- problem constants ----------------
#define NNODES_MAX 50000
#define EEDGES_MAX 500000
#define ETOT_MAX   (EEDGES_MAX + NNODES_MAX)
#define FIN    128
#define HID    384
#define NH     8
#define CH     48
#define NEG_SLOPE 0.2f

// ---------------- scratch (device globals; no allocation) ----------------
__device__ float d_xl[(size_t)NNODES_MAX * HID];
__device__ float d_xr[(size_t)NNODES_MAX * HID];
__device__ float d_h1[(size_t)NNODES_MAX * HID];
__device__ float d_h2[(size_t)NNODES_MAX * HID];
__device__ int   d_cnt[NNODES_MAX];
__device__ int   d_rowptr[NNODES_MAX + 1];
__device__ int   d_cur[NNODES_MAX];
__device__ int   d_csr[ETOT_MAX];

// ---------------- f32x2 helpers (sm_100+ packed fp32) ----------------
__device__ __forceinline__ unsigned long long pkf2(float x, float y) {
    unsigned long long r;
    asm("mov.b64 %0, {%1, %2};" : "=l"(r) : "f"(x), "f"(y));
    return r;
}
__device__ __forceinline__ void upkf2(float& x, float& y, unsigned long long v) {
    asm("mov.b64 {%0, %1}, %2;" : "=f"(x), "=f"(y) : "l"(v));
}
__device__ __forceinline__ void fma2(unsigned long long& d,
                                     unsigned long long a, unsigned long long b) {
    asm("fma.rn.f32x2 %0, %1, %2, %0;" : "+l"(d) : "l"(a), "l"(b));
}

// ---------------- helpers ----------------
__device__ __forceinline__ void edge_sd(const int* __restrict__ ei, int e, int E,
                                        int& s, int& d) {
    if (e < E) { s = ei[e]; d = ei[E + e]; }
    else       { s = e - E; d = s; }        // self loops appended
}

__global__ void zero_int_kernel(int* __restrict__ p, int n) {
    int i = blockIdx.x * blockDim.x + threadIdx.x;
    if (i < n) p[i] = 0;
}

// ---------------- CSR build ----------------
__global__ void hist_kernel(const int* __restrict__ ei, int* __restrict__ cnt,
                            int E, int Etot) {
    int e = blockIdx.x * blockDim.x + threadIdx.x;
    if (e >= Etot) return;
    int s, d;
    edge_sd(ei, e, E, s, d);
    atomicAdd(&cnt[d], 1);
}

// single-block exclusive scan over n elements
__global__ void scan_kernel(const int* __restrict__ cnt, int* __restrict__ rowptr,
                            int* __restrict__ cursor, int n) {
    __shared__ int sdata[1024];
    __shared__ int carry;
    int tid = threadIdx.x;
    if (tid == 0) { carry = 0; rowptr[0] = 0; }
    __syncthreads();
    for (int base = 0; base < n; base += 1024) {
        int i = base + tid;
        int v = (i < n) ? cnt[i] : 0;
        sdata[tid] = v;
        __syncthreads();
#pragma unroll
        for (int off = 1; off < 1024; off <<= 1) {
            int t = (tid >= off) ? sdata[tid - off] : 0;
            __syncthreads();
            sdata[tid] += t;
            __syncthreads();
        }
        if (i < n) {
            int incl = carry + sdata[tid];
            rowptr[i + 1] = incl;
            cursor[i] = incl - v;   // exclusive prefix = row start
        }
        __syncthreads();
        if (tid == 0) carry += sdata[1023];
        __syncthreads();
    }
}

__global__ void scatter_kernel(const int* __restrict__ ei, int* __restrict__ cursor,
                               int* __restrict__ csr, int E, int Etot) {
    int e = blockIdx.x * blockDim.x + threadIdx.x;
    if (e >= Etot) return;
    int s, d;
    edge_sd(ei, e, E, s, d);
    int pos = atomicAdd(&cursor[d], 1);
    csr[pos] = s;
}

// ---------------- GEMM: C[n,m] = A[n,k] @ W[k,m] + bias[m] ----------------
// 128x128 block tile, BK=8, 256 threads, 8x8 per-thread tile,
// double-buffered smem, fma.rn.f32x2 packed inner loop (2x FFMA throughput).
#define GBM 128
#define GBN 128
#define GBK 8

__global__ __launch_bounds__(256)
void gemm_bias2(const float* __restrict__ A, const float* __restrict__ W,
                const float* __restrict__ bias, float* __restrict__ C,
                int Nrows, int K, int M) {
    __shared__ float As[2][GBK][GBM + 4];
    __shared__ float Bs[2][GBK][GBN];

    const int block_row = blockIdx.x * GBM;
    const int block_col = blockIdx.y * GBN;
    const int tid = threadIdx.x;
    const int ty = tid >> 4;      // 0..15
    const int tx = tid & 15;      // 0..15

    // acc2[i][j] packs output cols (2j, 2j+1) for row i
    unsigned long long acc2[8][4];
#pragma unroll
    for (int i = 0; i < 8; i++)
#pragma unroll
        for (int j = 0; j < 4; j++) acc2[i][j] = 0ull;   // (0.0f, 0.0f)

    // A tile load mapping: one float4 per thread. 128 rows x 8 cols.
    const int arow = tid >> 1;
    const int acol = (tid & 1) * 4;
    const int grow = block_row + arow;
    // B tile load mapping: one float4 per thread. 8 rows x 128 cols.
    const int brl = tid >> 5;
    const int bcl = (tid & 31) * 4;

    const int ktiles = K / GBK;

    // preload tile 0
    {
        float4 av = make_float4(0.f, 0.f, 0.f, 0.f);
        if (grow < Nrows) av = *(const float4*)&A[(size_t)grow * K + acol];
        As[0][acol + 0][arow] = av.x;
        As[0][acol + 1][arow] = av.y;
        As[0][acol + 2][arow] = av.z;
        As[0][acol + 3][arow] = av.w;
        *(float4*)&Bs[0][brl][bcl] = *(const float4*)&W[(size_t)brl * M + block_col + bcl];
    }
    __syncthreads();

    int buf = 0;
    for (int t = 0; t < ktiles; t++) {
        const bool has_next = (t + 1 < ktiles);
        float4 avn = make_float4(0.f, 0.f, 0.f, 0.f);
        float4 bvn = make_float4(0.f, 0.f, 0.f, 0.f);
        if (has_next) {
            const int k0n = (t + 1) * GBK;
            if (grow < Nrows) avn = *(const float4*)&A[(size_t)grow * K + k0n + acol];
            bvn = *(const float4*)&W[(size_t)(k0n + brl) * M + block_col + bcl];
        }

#pragma unroll
        for (int kk = 0; kk < GBK; kk++) {
            float4 a0 = *(const float4*)&As[buf][kk][ty * 8];
            float4 a1 = *(const float4*)&As[buf][kk][ty * 8 + 4];
            float4 b0 = *(const float4*)&Bs[buf][kk][tx * 8];
            float4 b1 = *(const float4*)&Bs[buf][kk][tx * 8 + 4];
            unsigned long long bp[4] = {
                pkf2(b0.x, b0.y), pkf2(b0.z, b0.w),
                pkf2(b1.x, b1.y), pkf2(b1.z, b1.w)
            };
            float ra[8] = {a0.x, a0.y, a0.z, a0.w, a1.x, a1.y, a1.z, a1.w};
#pragma unroll
            for (int i = 0; i < 8; i++) {
                unsigned long long ad = pkf2(ra[i], ra[i]);
#pragma unroll
                for (int j = 0; j < 4; j++) fma2(acc2[i][j], ad, bp[j]);
            }
        }

        if (has_next) {
            const int nb = buf ^ 1;
            As[nb][acol + 0][arow] = avn.x;
            As[nb][acol + 1][arow] = avn.y;
            As[nb][acol + 2][arow] = avn.z;
            As[nb][acol + 3][arow] = avn.w;
            *(float4*)&Bs[nb][brl][bcl] = bvn;
        }
        __syncthreads();
        buf ^= 1;
    }

#pragma unroll
    for (int i = 0; i < 8; i++) {
        int r = block_row + ty * 8 + i;
        if (r < Nrows) {
            int c0 = block_col + tx * 8;
            float o[8];
#pragma unroll
            for (int j = 0; j < 4; j++) upkf2(o[2 * j], o[2 * j + 1], acc2[i][j]);
            float4 o0, o1;
            o0.x = o[0] + bias[c0 + 0];
            o0.y = o[1] + bias[c0 + 1];
            o0.z = o[2] + bias[c0 + 2];
            o0.w = o[3] + bias[c0 + 3];
            o1.x = o[4] + bias[c0 + 4];
            o1.y = o[5] + bias[c0 + 5];
            o1.z = o[6] + bias[c0 + 6];
            o1.w = o[7] + bias[c0 + 7];
            *(float4*)&C[(size_t)r * M + c0]     = o0;
            *(float4*)&C[(size_t)r * M + c0 + 4] = o1;
        }
    }
}

// ---------------- fused per-node GATv2 edge phase (layers 1,2) ----------------
// one warp per node; lane owns 12 contiguous channels (1/4 of one head).
// Pairwise online softmax: merge 2 edges per chain step, prefetch next pair.
__global__ __launch_bounds__(256)
void gat_node_kernel(const float* __restrict__ xl, const float* __restrict__ xr,
                     const float* __restrict__ att, const float* __restrict__ bias,
                     const int* __restrict__ rowptr, const int* __restrict__ csr,
                     float* __restrict__ out, int n) {
    int node = (blockIdx.x * blockDim.x + threadIdx.x) >> 5;
    if (node >= n) return;
    int lane = threadIdx.x & 31;

    const float4* pr = (const float4*)(xr + (size_t)node * HID) + lane * 3;
    float4 r0 = __ldg(pr), r1 = __ldg(pr + 1), r2 = __ldg(pr + 2);
    const float4* pa = (const float4*)att + lane * 3;
    float4 aw0 = __ldg(pa), aw1 = __ldg(pa + 1), aw2 = __ldg(pa + 2);

    float ra[12] = {r0.x, r0.y, r0.z, r0.w, r1.x, r1.y, r1.z, r1.w, r2.x, r2.y, r2.z, r2.w};
    float wa[12] = {aw0.x, aw0.y, aw0.z, aw0.w, aw1.x, aw1.y, aw1.z, aw1.w, aw2.x, aw2.y, aw2.z, aw2.w};

    float m = -INFINITY, ssum = 0.0f;
    float acc[12];
#pragma unroll
    for (int k = 0; k < 12; k++) acc[k] = 0.0f;

    const int jbeg = __ldg(&rowptr[node]), jend = __ldg(&rowptr[node + 1]);

    // prefetch first pair
    float4 nA0, nA1, nA2, nB0, nB1, nB2;
    if (jbeg + 1 < jend) {
        int sA = __ldg(&csr[jbeg]), sB = __ldg(&csr[jbeg + 1]);
        const float4* plA = (const float4*)(xl + (size_t)sA * HID) + lane * 3;
        const float4* plB = (const float4*)(xl + (size_t)sB * HID) + lane * 3;
        nA0 = __ldg(plA); nA1 = __ldg(plA + 1); nA2 = __ldg(plA + 2);
        nB0 = __ldg(plB); nB1 = __ldg(plB + 1); nB2 = __ldg(plB + 2);
    }

    int j = jbeg;
    for (; j + 1 < jend; j += 2) {
        float4 A0 = nA0, A1 = nA1, A2 = nA2;
        float4 B0 = nB0, B1 = nB1, B2 = nB2;
        if (j + 3 < jend) {
            int sA = __ldg(&csr[j + 2]), sB = __ldg(&csr[j + 3]);
            const float4* plA = (const float4*)(xl + (size_t)sA * HID) + lane * 3;
            const float4* plB = (const float4*)(xl + (size_t)sB * HID) + lane * 3;
            nA0 = __ldg(plA); nA1 = __ldg(plA + 1); nA2 = __ldg(plA + 2);
            nB0 = __ldg(plB); nB1 = __ldg(plB + 1); nB2 = __ldg(plB + 2);
        }
        float la[12] = {A0.x, A0.y, A0.z, A0.w, A1.x, A1.y, A1.z, A1.w, A2.x, A2.y, A2.z, A2.w};
        float lb[12] = {B0.x, B0.y, B0.z, B0.w, B1.x, B1.y, B1.z, B1.w, B2.x, B2.y, B2.z, B2.w};

        float sa = 0.0f, sb = 0.0f;
#pragma unroll
        for (int k = 0; k < 12; k++) {
            float mva = la[k] + ra[k];
            float mvb = lb[k] + ra[k];
            sa += (mva > 0.f ? mva : NEG_SLOPE * mva) * wa[k];
            sb += (mvb > 0.f ? mvb : NEG_SLOPE * mvb) * wa[k];
        }
        // reduce over the 4 lanes of this head (lane groups aligned mod 4)
        sa += __shfl_xor_sync(0xffffffffu, sa, 1);
        sb += __shfl_xor_sync(0xffffffffu, sb, 1);
        sa += __shfl_xor_sync(0xffffffffu, sa, 2);
        sb += __shfl_xor_sync(0xffffffffu, sb, 2);

        float pm = fmaxf(sa, sb);
        float ea = __expf(sa - pm), eb = __expf(sb - pm);
        float newm = fmaxf(m, pm);
        float sc = __expf(m - newm);       // 0 on first pair (m=-inf)
        float pc = __expf(pm - newm);
        ssum = ssum * sc + (ea + eb) * pc;
        float wA = ea * pc, wB = eb * pc;
#pragma unroll
        for (int k = 0; k < 12; k++)
            acc[k] = acc[k] * sc + wA * la[k] + wB * lb[k];
        m = newm;
    }
    if (j < jend) {   // odd tail (or single edge)
        int s = __ldg(&csr[j]);
        const float4* pl = (const float4*)(xl + (size_t)s * HID) + lane * 3;
        float4 A0 = __ldg(pl), A1 = __ldg(pl + 1), A2 = __ldg(pl + 2);
        float la[12] = {A0.x, A0.y, A0.z, A0.w, A1.x, A1.y, A1.z, A1.w, A2.x, A2.y, A2.z, A2.w};
        float sa = 0.0f;
#pragma unroll
        for (int k = 0; k < 12; k++) {
            float mv = la[k] + ra[k];
            sa += (mv > 0.f ? mv : NEG_SLOPE * mv) * wa[k];
        }
        sa += __shfl_xor_sync(0xffffffffu, sa, 1);
        sa += __shfl_xor_sync(0xffffffffu, sa, 2);
        float newm = fmaxf(m, sa);
        float sc = __expf(m - newm);
        float p = __expf(sa - newm);
        ssum = ssum * sc + p;
#pragma unroll
        for (int k = 0; k < 12; k++) acc[k] = acc[k] * sc + p * la[k];
        m = newm;
    }

    float inv = 1.0f / (ssum + 1e-16f);
    const float4* pb = (const float4*)bias + lane * 3;
    float4 b0 = __ldg(pb), b1 = __ldg(pb + 1), b2 = __ldg(pb + 2);
    float ba[12] = {b0.x, b0.y, b0.z, b0.w, b1.x, b1.y, b1.z, b1.w, b2.x, b2.y, b2.z, b2.w};

    float o[12];
#pragma unroll
    for (int k = 0; k < 12; k++) {
        float v = acc[k] * inv + ba[k];
        o[k] = v > 0.0f ? v : expm1f(v);   // ELU
    }
    float4* po = (float4*)(out + (size_t)node * HID) + lane * 3;
    po[0] = make_float4(o[0], o[1], o[2], o[3]);
    po[1] = make_float4(o[4], o[5], o[6], o[7]);
    po[2] = make_float4(o[8], o[9], o[10], o[11]);
}

// ---------------- layer 3: linear 384 -> 2 (Wl and Wr fused) ----------------
__global__ void lin3_kernel(const float* __restrict__ h,
                            const float* __restrict__ Wl, const float* __restrict__ bl,
                            const float* __restrict__ Wr, const float* __restrict__ br,
                            float* __restrict__ xl3, float* __restrict__ xr3, int n) {
    int w = (blockIdx.x * blockDim.x + threadIdx.x) >> 5;
    if (w >= n) return;
    int lane = threadIdx.x & 31;
    const float* row = h + (size_t)w * HID;
    float l0 = 0.f, l1 = 0.f, r0 = 0.f, r1 = 0.f;
    for (int k = lane; k < HID; k += 32) {
        float a = row[k];
        l0 += a * Wl[2 * k];     l1 += a * Wl[2 * k + 1];
        r0 += a * Wr[2 * k];     r1 += a * Wr[2 * k + 1];
    }
#pragma unroll
    for (int o = 16; o > 0; o >>= 1) {
        l0 += __shfl_xor_sync(0xffffffffu, l0, o);
        l1 += __shfl_xor_sync(0xffffffffu, l1, o);
        r0 += __shfl_xor_sync(0xffffffffu, r0, o);
        r1 += __shfl_xor_sync(0xffffffffu, r1, o);
    }
    if (lane == 0) {
        xl3[2 * w]     = l0 + bl[0];
        xl3[2 * w + 1] = l1 + bl[1];
        xr3[2 * w]     = r0 + br[0];
        xr3[2 * w + 1] = r1 + br[1];
    }
}

// ---------------- layer 3 fused node kernel (1 head, 2 ch) + log_softmax ----------------
__global__ void gat3_node_kernel(const float* __restrict__ xl3, const float* __restrict__ xr3,
                                 const float* __restrict__ att3, const float* __restrict__ bias3,
                                 const int* __restrict__ rowptr, const int* __restrict__ csr,
                                 float* __restrict__ out, int n) {
    int node = blockIdx.x * blockDim.x + threadIdx.x;
    if (node >= n) return;
    float rx0 = xr3[2 * node], rx1 = xr3[2 * node + 1];
    float w0 = att3[0], w1 = att3[1];
    float m = -INFINITY, ssum = 0.f, acc0 = 0.f, acc1 = 0.f;
    int jbeg = rowptr[node], jend = rowptr[node + 1];
    for (int j = jbeg; j < jend; j++) {
        int s = csr[j];
        float l0 = xl3[2 * s], l1 = xl3[2 * s + 1];
        float m0 = l0 + rx0, m1 = l1 + rx1;
        float sc = (m0 > 0.f ? m0 : NEG_SLOPE * m0) * w0
                 + (m1 > 0.f ? m1 : NEG_SLOPE * m1) * w1;
        float newm = fmaxf(m, sc);
        float scale = __expf(m - newm);
        float p = __expf(sc - newm);
        ssum = ssum * scale + p;
        acc0 = acc0 * scale + p * l0;
        acc1 = acc1 * scale + p * l1;
        m = newm;
    }
    float inv = 1.0f / (ssum + 1e-16f);
    float a = acc0 * inv + bias3[0];
    float b = acc1 * inv + bias3[1];
    float mm = fmaxf(a, b);
    float l = mm + logf(expf(a - mm) + expf(b - mm));
    out[2 * node]     = a - l;
    out[2 * node + 1] = b - l;
}

// ---------------- host side ----------------
static inline int cdiv(int a, int b) { return (a + b - 1) / b; }

extern "C" void kernel_launch(void* const* d_in, const int* in_sizes, int n_in,
                              void* d_out, int out_size) {
    const float* x   = (const float*)d_in[0];
    const int*   ei  = (const int*)d_in[1];
    const float* Wl1 = (const float*)d_in[2];
    const float* bl1 = (const float*)d_in[3];
    const float* Wr1 = (const float*)d_in[4];
    const float* br1 = (const float*)d_in[5];
    const float* att1  = (const float*)d_in[6];
    const float* bias1 = (const float*)d_in[7];
    const float* Wl2 = (const float*)d_in[8];
    const float* bl2 = (const float*)d_in[9];
    const float* Wr2 = (const float*)d_in[10];
    const float* br2 = (const float*)d_in[11];
    const float* att2  = (const float*)d_in[12];
    const float* bias2 = (const float*)d_in[13];
    const float* Wl3 = (const float*)d_in[14];
    const float* bl3 = (const float*)d_in[15];
    const float* Wr3 = (const float*)d_in[16];
    const float* br3 = (const float*)d_in[17];
    const float* att3  = (const float*)d_in[18];
    const float* bias3 = (const float*)d_in[19];

    const int n    = in_sizes[0] / FIN;       // 50000
    const int E    = in_sizes[1] / 2;         // 500000
    const int Etot = E + n;                   // 550000

    float *xl, *xr, *h1, *h2;
    int *cnt, *rowptr, *cur, *csr;
    cudaGetSymbolAddress((void**)&xl, d_xl);
    cudaGetSymbolAddress((void**)&xr, d_xr);
    cudaGetSymbolAddress((void**)&h1, d_h1);
    cudaGetSymbolAddress((void**)&h2, d_h2);
    cudaGetSymbolAddress((void**)&cnt, d_cnt);
    cudaGetSymbolAddress((void**)&rowptr, d_rowptr);
    cudaGetSymbolAddress((void**)&cur, d_cur);
    cudaGetSymbolAddress((void**)&csr, d_csr);
    float* out = (float*)d_out;

    dim3 gg(cdiv(n, GBM), HID / GBN);

    // ---- CSR build interleaved with layer-1 GEMMs (GEMM at profile window) ----
    zero_int_kernel<<<cdiv(n, 256), 256>>>(cnt, n);
    hist_kernel<<<cdiv(Etot, 256), 256>>>(ei, cnt, E, Etot);
    scan_kernel<<<1, 1024>>>(cnt, rowptr, cur, n);
    gemm_bias2<<<gg, 256>>>(x, Wl1, bl1, xl, n, FIN, HID);
    gemm_bias2<<<gg, 256>>>(x, Wr1, br1, xr, n, FIN, HID);
    scatter_kernel<<<cdiv(Etot, 256), 256>>>(ei, cur, csr, E, Etot);

    // ---- layer 1 edge phase ----
    gat_node_kernel<<<cdiv(n * 32, 256), 256>>>(xl, xr, att1, bias1, rowptr, csr, h1, n);

    // ---- layer 2: h1 (384) -> h2 (384) ----
    gemm_bias2<<<gg, 256>>>(h1, Wl2, bl2, xl, n, HID, HID);
    gemm_bias2<<<gg, 256>>>(h1, Wr2, br2, xr, n, HID, HID);
    gat_node_kernel<<<cdiv(n * 32, 256), 256>>>(xl, xr, att2, bias2, rowptr, csr, h2, n);

    // ---- layer 3: h2 (384) -> 2, 1 head, concat=False, + log_softmax ----
    lin3_kernel<<<cdiv(n * 32, 256), 256>>>(h2, Wl3, bl3, Wr3, br3, xl, xr, n);
    gat3_node_kernel<<<cdiv(n, 256), 256>>>(xl, xr, att3, bias3, rowptr, csr, out, n);
}